// round 3
// baseline (speedup 1.0000x reference)
#include <cuda_runtime.h>

// out = tanh(in @ Lr^T + br) + in @ Ld^T + bd + in
// Lr = diag(colsum(Wr)) - Wr with Wr[ei,ej] += wr
// Ld = diag(colsum(Wd)) - Wd with Wd[ej,ei] += wd
//
// Dense formulation: build S[m][n] = (G,H) interleaved where
//   G[m][n] = Lr[n][m]  (so reaction[b,n] = sum_m in[b,m]*G[m][n])
//   H[m][n] = Ld[n][m]
// Then a coalesced thread-per-node GEMM with smem-broadcast input rows.

#define NN 207
#define NE 1722
#define BATCH 64
#define NB 2                 // batch rows per CTA in main kernel
#define PITCH (2 * NN)       // floats per m-row: interleaved (G,H)
#define S_FLOATS (NN * PITCH)        // 85698
#define S_PAD4   ((S_FLOATS + 7) & ~3) // 85704, divisible by 4

__device__ __align__(16) float g_S[S_PAD4];

// ---------------- zero scratch ----------------
__global__ __launch_bounds__(256)
void zero_k() {
    int i = blockIdx.x * blockDim.x + threadIdx.x;
    float4* p = reinterpret_cast<float4*>(g_S);
    if (i < S_PAD4 / 4) p[i] = make_float4(0.f, 0.f, 0.f, 0.f);
}

// ---------------- scatter edges into dense transposed Laplacians ----------------
__global__ __launch_bounds__(256)
void scatter_k(const float* __restrict__ wr, const float* __restrict__ wd,
               const int* __restrict__ ei, const int* __restrict__ ej) {
    int k = blockIdx.x * blockDim.x + threadIdx.x;
    if (k >= NE) return;
    const int i = ei[k];
    const int j = ej[k];
    const float vr = wr[k];
    const float vd = wd[k];
    // G[m][n] = Lr[n][m]:  Lr[i][j] -= vr  -> m=j, n=i ;  Lr[j][j] += vr -> m=n=j
    atomicAdd(&g_S[j * PITCH + 2 * i + 0], -vr);
    atomicAdd(&g_S[j * PITCH + 2 * j + 0],  vr);
    // H[m][n] = Ld[n][m]:  Ld[j][i] -= vd  -> m=i, n=j ;  Ld[i][i] += vd -> m=n=i
    atomicAdd(&g_S[i * PITCH + 2 * j + 1], -vd);
    atomicAdd(&g_S[i * PITCH + 2 * i + 1],  vd);
}

// ---------------- main: dense GEMM + epilogue ----------------
__global__ __launch_bounds__(224)
void main_k(const float* __restrict__ in,
            const float* __restrict__ br,
            const float* __restrict__ bd,
            float* __restrict__ out) {
    __shared__ float s_in[NB][NN];
    const int b0 = blockIdx.x * NB;
    const int n  = threadIdx.x;

    if (n < NN) {
        #pragma unroll
        for (int r = 0; r < NB; r++)
            s_in[r][n] = in[(b0 + r) * NN + n];
    }
    __syncthreads();

    if (n < NN) {
        const float2* __restrict__ S2 = reinterpret_cast<const float2*>(g_S);
        float ar0 = 0.f, ar1 = 0.f, ad0 = 0.f, ad1 = 0.f;
        #pragma unroll 4
        for (int m = 0; m < NN; m++) {
            const float2 gh = S2[m * NN + n];   // coalesced: (G[m][n], H[m][n])
            const float x0 = s_in[0][m];        // smem broadcast
            const float x1 = s_in[1][m];
            ar0 = fmaf(x0, gh.x, ar0);
            ad0 = fmaf(x0, gh.y, ad0);
            ar1 = fmaf(x1, gh.x, ar1);
            ad1 = fmaf(x1, gh.y, ad1);
        }
        const float brn = br[n];
        const float bdn = bd[n];
        out[(b0 + 0) * NN + n] = tanhf(ar0 + brn) + ad0 + bdn + s_in[0][n];
        out[(b0 + 1) * NN + n] = tanhf(ar1 + brn) + ad1 + bdn + s_in[1][n];
    }
}

extern "C" void kernel_launch(void* const* d_in, const int* in_sizes, int n_in,
                              void* d_out, int out_size) {
    const float* in_ = (const float*)d_in[0];
    const float* wr  = (const float*)d_in[1];
    const float* wd  = (const float*)d_in[2];
    const float* br  = (const float*)d_in[3];
    const float* bd  = (const float*)d_in[4];
    const int*   ei  = (const int*)d_in[5];
    const int*   ej  = (const int*)d_in[6];
    float* out = (float*)d_out;

    zero_k<<<(S_PAD4 / 4 + 255) / 256, 256>>>();
    scatter_k<<<(NE + 255) / 256, 256>>>(wr, wd, ei, ej);
    main_k<<<BATCH / NB, 224>>>(in_, br, bd, out);
}